// round 7
// baseline (speedup 1.0000x reference)
#include <cuda_runtime.h>

#define N_NODES 100000
#define N_EDGES 1600000
#define D 64
#define BN_EPS 1e-5f

#define SCAN_B 1024
#define NBLK ((N_NODES + SCAN_B - 1) / SCAN_B)   // 98

// ---------------- device scratch (no allocations allowed) ----------------
__device__ float g_support[N_NODES * D];   // x @ W
__device__ float g_agg[N_NODES * D];       // aggregated messages
__device__ int   g_deg[N_NODES];           // in-degree histogram
__device__ int   g_rowptr[N_NODES + 1];    // CSR row pointers (by dst)
__device__ int   g_cursor[N_NODES];        // scatter write cursors
__device__ int   g_blockSums[128];
__device__ int2  g_perm[N_EDGES];          // packed (src, w-bits), dst-grouped
__device__ float g_colsum[D];
__device__ float g_colsq[D];

// ---------------- 0: zero histogram + stats accumulators ----------------
__global__ void zero_kernel() {
    int i = blockIdx.x * blockDim.x + threadIdx.x;
    if (i < N_NODES) g_deg[i] = 0;
    if (i < D) { g_colsum[i] = 0.f; g_colsq[i] = 0.f; }
}

// ---------------- 1: support = x @ W  +  dst histogram (fused) -----------
// block = 256 threads = 16 rows x 16 col-groups (float4 per thread).
// grid = 6250 blocks -> exactly N_EDGES threads for the fused histogram.
__global__ void gemm_hist_kernel(const float* __restrict__ x,
                                 const float* __restrict__ W,
                                 const int* __restrict__ edge_dst) {
    __shared__ float4 Ws4[64 * 16];     // W[k][c] as float4 over c
    __shared__ float  xs[16][65];       // padded to kill bank conflicts

    int tid = threadIdx.x;

    // fused histogram: one edge per thread (independent of the GEMM work)
    int e = blockIdx.x * 256 + tid;
    atomicAdd(&g_deg[__ldg(&edge_dst[e])], 1);

    const float4* W4 = (const float4*)W;
    #pragma unroll
    for (int i = tid; i < 1024; i += 256) Ws4[i] = W4[i];

    int row0 = blockIdx.x * 16;
    {   // 16 rows x 64 floats = 256 float4, one per thread
        const float4* x4 = (const float4*)(x + (size_t)row0 * D);
        float4 v = x4[tid];
        int r = tid >> 4, k4 = tid & 15;
        xs[r][k4 * 4 + 0] = v.x; xs[r][k4 * 4 + 1] = v.y;
        xs[r][k4 * 4 + 2] = v.z; xs[r][k4 * 4 + 3] = v.w;
    }
    __syncthreads();

    int r = tid >> 4, c4 = tid & 15;
    float4 acc = {0.f, 0.f, 0.f, 0.f};
    #pragma unroll
    for (int k = 0; k < 64; k++) {
        float xv = xs[r][k];
        float4 w = Ws4[k * 16 + c4];
        acc.x += xv * w.x; acc.y += xv * w.y;
        acc.z += xv * w.z; acc.w += xv * w.w;
    }
    ((float4*)g_support)[(size_t)(row0 + r) * 16 + c4] = acc;
}

// ---------------- 2: per-block exclusive scan (shuffle-based) -------------
__global__ void scan_block_kernel() {
    __shared__ int warpSum[32];
    int t = threadIdx.x;
    int i = blockIdx.x * SCAN_B + t;
    int v = (i < N_NODES) ? g_deg[i] : 0;
    int lane = t & 31, wid = t >> 5;

    int s = v;                                  // warp inclusive scan
    #pragma unroll
    for (int off = 1; off < 32; off <<= 1) {
        int n = __shfl_up_sync(0xffffffffu, s, off);
        if (lane >= off) s += n;
    }
    if (lane == 31) warpSum[wid] = s;
    __syncthreads();
    if (wid == 0) {                             // scan the 32 warp sums
        int w = warpSum[lane];
        #pragma unroll
        for (int off = 1; off < 32; off <<= 1) {
            int n = __shfl_up_sync(0xffffffffu, w, off);
            if (lane >= off) w += n;
        }
        warpSum[lane] = w;                      // inclusive
    }
    __syncthreads();
    int base = wid ? warpSum[wid - 1] : 0;
    if (i < N_NODES) g_rowptr[i] = base + s - v;         // exclusive in-block
    if (t == SCAN_B - 1) g_blockSums[blockIdx.x] = base + s;
}

// ---------------- 3: add block prefix (computed in-block), init cursors ---
__global__ void add_offsets_kernel() {
    __shared__ int s_prefix;
    int b = blockIdx.x, t = threadIdx.x;
    if (t < 32) {
        int p = 0;
        for (int j = t; j < b; j += 32) p += g_blockSums[j];
        #pragma unroll
        for (int o = 16; o; o >>= 1) p += __shfl_down_sync(0xffffffffu, p, o);
        if (t == 0) s_prefix = p;
    }
    __syncthreads();
    int i = b * SCAN_B + t;
    if (i < N_NODES) {
        int r = g_rowptr[i] + s_prefix;
        g_rowptr[i] = r;
        g_cursor[i] = r;
    }
    if (i == 0) g_rowptr[N_NODES] = N_EDGES;
}

// ---------------- 4: scatter edges into dst-grouped order (packed) --------
__global__ void scatter_kernel(const int* __restrict__ edge_src,
                               const int* __restrict__ edge_dst,
                               const float* __restrict__ edge_weight) {
    int e = blockIdx.x * blockDim.x + threadIdx.x;
    if (e < N_EDGES) {
        int d = __ldg(&edge_dst[e]);
        int s = __ldg(&edge_src[e]);
        float w = __ldg(&edge_weight[e]);
        int pos = atomicAdd(&g_cursor[d], 1);
        g_perm[pos] = make_int2(s, __float_as_int(w));
    }
}

// ---------------- 5: gather-aggregate + fused BN statistics ---------------
// 16 threads/node, float4 each. 2x pipelined gathers for MLP.
// grid = 6250 blocks x 256 threads -> exactly N_NODES*16 threads (no guard).
__global__ void aggregate_kernel() {
    int tid = threadIdx.x;
    int gt = blockIdx.x * 256 + tid;
    int node = gt >> 4;
    int lane = gt & 15;
    int beg = __ldg(&g_rowptr[node]);
    int end = __ldg(&g_rowptr[node + 1]);
    const float4* sup4 = (const float4*)g_support;
    float4 acc = {0.f, 0.f, 0.f, 0.f};

    int e = beg;
    for (; e + 1 < end; e += 2) {       // issue both gathers before consuming
        int2 p0 = __ldg(&g_perm[e]);
        int2 p1 = __ldg(&g_perm[e + 1]);
        float4 v0 = sup4[(size_t)p0.x * 16 + lane];
        float4 v1 = sup4[(size_t)p1.x * 16 + lane];
        float w0 = __int_as_float(p0.y);
        float w1 = __int_as_float(p1.y);
        acc.x += w0 * v0.x; acc.y += w0 * v0.y;
        acc.z += w0 * v0.z; acc.w += w0 * v0.w;
        acc.x += w1 * v1.x; acc.y += w1 * v1.y;
        acc.z += w1 * v1.z; acc.w += w1 * v1.w;
    }
    if (e < end) {
        int2 p = __ldg(&g_perm[e]);
        float w = __int_as_float(p.y);
        float4 v = sup4[(size_t)p.x * 16 + lane];
        acc.x += w * v.x; acc.y += w * v.y;
        acc.z += w * v.z; acc.w += w * v.w;
    }
    ((float4*)g_agg)[(size_t)node * 16 + lane] = acc;

    // ---- fused column stats: reduce over the 16 nodes in this block ----
    __shared__ float4 shS[256], shQ[256];
    shS[tid] = acc;
    shQ[tid] = make_float4(acc.x * acc.x, acc.y * acc.y,
                           acc.z * acc.z, acc.w * acc.w);
    __syncthreads();
    #pragma unroll
    for (int s = 128; s >= 16; s >>= 1) {   // preserves lane congruence mod 16
        if (tid < s) {
            float4 a = shS[tid], b = shS[tid + s];
            shS[tid] = make_float4(a.x + b.x, a.y + b.y, a.z + b.z, a.w + b.w);
            float4 c = shQ[tid], d = shQ[tid + s];
            shQ[tid] = make_float4(c.x + d.x, c.y + d.y, c.z + d.z, c.w + d.w);
        }
        __syncthreads();
    }
    if (tid < 16) {
        float4 s4 = shS[tid], q4 = shQ[tid];
        int c = tid * 4;
        atomicAdd(&g_colsum[c + 0], s4.x); atomicAdd(&g_colsum[c + 1], s4.y);
        atomicAdd(&g_colsum[c + 2], s4.z); atomicAdd(&g_colsum[c + 3], s4.w);
        atomicAdd(&g_colsq[c + 0], q4.x);  atomicAdd(&g_colsq[c + 1], q4.y);
        atomicAdd(&g_colsq[c + 2], q4.z);  atomicAdd(&g_colsq[c + 3], q4.w);
    }
}

// ---------------- 6: finalize BN in-block + normalize + ReLU --------------
// bias cancels with the batch mean, so it never appears.
__global__ void out_kernel(const float* __restrict__ gamma,
                           const float* __restrict__ beta,
                           float* __restrict__ out) {
    __shared__ float s_scale[64], s_shift[64];
    int tid = threadIdx.x;
    if (tid < 64) {
        float mean = g_colsum[tid] * (1.f / N_NODES);
        float var  = g_colsq[tid] * (1.f / N_NODES) - mean * mean;
        float inv  = rsqrtf(var + BN_EPS);
        float sc   = __ldg(&gamma[tid]) * inv;
        s_scale[tid] = sc;
        s_shift[tid] = __ldg(&beta[tid]) - mean * sc;
    }
    __syncthreads();
    int i = blockIdx.x * 256 + tid;            // grid covers N_NODES*16 exactly
    int c = (i & 15) * 4;
    float4 a = ((const float4*)g_agg)[i];
    float4 o;
    o.x = fmaxf(fmaf(a.x, s_scale[c + 0], s_shift[c + 0]), 0.f);
    o.y = fmaxf(fmaf(a.y, s_scale[c + 1], s_shift[c + 1]), 0.f);
    o.z = fmaxf(fmaf(a.z, s_scale[c + 2], s_shift[c + 2]), 0.f);
    o.w = fmaxf(fmaf(a.w, s_scale[c + 3], s_shift[c + 3]), 0.f);
    ((float4*)out)[i] = o;
}

// ---------------- launcher -------------------------------------------------
extern "C" void kernel_launch(void* const* d_in, const int* in_sizes, int n_in,
                              void* d_out, int out_size) {
    const float* x           = (const float*)d_in[0];
    const int*   edge_src    = (const int*)d_in[1];
    const int*   edge_dst    = (const int*)d_in[2];
    const float* edge_weight = (const float*)d_in[3];
    const float* W           = (const float*)d_in[4];
    // d_in[5] = bias: mathematically cancels inside BatchNorm — unused.
    const float* gamma       = (const float*)d_in[6];
    const float* beta        = (const float*)d_in[7];
    float*       out         = (float*)d_out;

    zero_kernel<<<(N_NODES + 255) / 256, 256>>>();
    gemm_hist_kernel<<<N_NODES / 16, 256>>>(x, W, edge_dst);   // 6250 blocks
    scan_block_kernel<<<NBLK, SCAN_B>>>();
    add_offsets_kernel<<<NBLK, SCAN_B>>>();
    scatter_kernel<<<(N_EDGES + 511) / 512, 512>>>(edge_src, edge_dst, edge_weight);
    aggregate_kernel<<<N_NODES * 16 / 256, 256>>>();           // 6250 blocks
    out_kernel<<<N_NODES * 16 / 256, 256>>>(gamma, beta, out); // 6250 blocks
}

// round 10
// speedup vs baseline: 1.8692x; 1.8692x over previous
#include <cuda_runtime.h>

#define N_NODES 100000
#define N_EDGES 1600000
#define D 64
#define BN_EPS 1e-5f

#define SCAN_B 1024
#define NBLK ((N_NODES + SCAN_B - 1) / SCAN_B)   // 98

// ---------------- device scratch (no allocations allowed) ----------------
__device__ float g_support[N_NODES * D];   // x @ W
__device__ float g_agg[N_NODES * D];       // aggregated messages
__device__ int   g_deg[N_NODES];           // in-degree histogram
__device__ int   g_rowptr[N_NODES + 1];    // CSR row pointers (by dst)
__device__ int   g_cursor[N_NODES];        // scatter write cursors
__device__ int   g_blockSums[128];
__device__ int2  g_perm[N_EDGES];          // packed (src, w-bits), dst-grouped
__device__ float g_colsum[D];
__device__ float g_colsq[D];

// ---------------- 0: zero histogram + stats accumulators ----------------
__global__ void zero_kernel() {
    int i = blockIdx.x * blockDim.x + threadIdx.x;
    if (i < N_NODES) g_deg[i] = 0;
    if (i < D) { g_colsum[i] = 0.f; g_colsq[i] = 0.f; }
}

// ---------------- 1: support = x @ W  (fp32 SIMT, W in smem) -------------
// block = 256 threads = 16 rows x 16 col-groups (float4 per thread)
__global__ void gemm_kernel(const float* __restrict__ x,
                            const float* __restrict__ W) {
    __shared__ float4 Ws4[64 * 16];     // W[k][c] as float4 over c
    __shared__ float  xs[16][65];       // padded to kill bank conflicts

    int tid = threadIdx.x;
    const float4* W4 = (const float4*)W;
    #pragma unroll
    for (int i = tid; i < 1024; i += 256) Ws4[i] = W4[i];

    int row0 = blockIdx.x * 16;
    {   // 16 rows x 64 floats = 256 float4, one per thread
        const float4* x4 = (const float4*)(x + (size_t)row0 * D);
        float4 v = x4[tid];
        int r = tid >> 4, k4 = tid & 15;
        xs[r][k4 * 4 + 0] = v.x; xs[r][k4 * 4 + 1] = v.y;
        xs[r][k4 * 4 + 2] = v.z; xs[r][k4 * 4 + 3] = v.w;
    }
    __syncthreads();

    int r = tid >> 4, c4 = tid & 15;
    float4 acc = {0.f, 0.f, 0.f, 0.f};
    #pragma unroll
    for (int k = 0; k < 64; k++) {
        float xv = xs[r][k];
        float4 w = Ws4[k * 16 + c4];
        acc.x += xv * w.x; acc.y += xv * w.y;
        acc.z += xv * w.z; acc.w += xv * w.w;
    }
    ((float4*)g_support)[(size_t)(row0 + r) * 16 + c4] = acc;
}

// ---------------- 2: histogram of edge destinations ----------------------
__global__ void hist_kernel(const int* __restrict__ edge_dst) {
    int e = blockIdx.x * blockDim.x + threadIdx.x;
    if (e < N_EDGES) atomicAdd(&g_deg[__ldg(&edge_dst[e])], 1);
}

// ---------------- 3: per-block exclusive scan (shuffle-based) -------------
__global__ void scan_block_kernel() {
    __shared__ int warpSum[32];
    int t = threadIdx.x;
    int i = blockIdx.x * SCAN_B + t;
    int v = (i < N_NODES) ? g_deg[i] : 0;
    int lane = t & 31, wid = t >> 5;

    int s = v;                                  // warp inclusive scan
    #pragma unroll
    for (int off = 1; off < 32; off <<= 1) {
        int n = __shfl_up_sync(0xffffffffu, s, off);
        if (lane >= off) s += n;
    }
    if (lane == 31) warpSum[wid] = s;
    __syncthreads();
    if (wid == 0) {                             // scan the 32 warp sums
        int w = warpSum[lane];
        #pragma unroll
        for (int off = 1; off < 32; off <<= 1) {
            int n = __shfl_up_sync(0xffffffffu, w, off);
            if (lane >= off) w += n;
        }
        warpSum[lane] = w;                      // inclusive
    }
    __syncthreads();
    int base = wid ? warpSum[wid - 1] : 0;
    if (i < N_NODES) g_rowptr[i] = base + s - v;         // exclusive in-block
    if (t == SCAN_B - 1) g_blockSums[blockIdx.x] = base + s;
}

// ---------------- 4: add block prefix (computed in-block), init cursors ---
__global__ void add_offsets_kernel() {
    __shared__ int s_prefix;
    int b = blockIdx.x, t = threadIdx.x;
    if (t < 32) {
        int p = 0;
        for (int j = t; j < b; j += 32) p += g_blockSums[j];
        #pragma unroll
        for (int o = 16; o; o >>= 1) p += __shfl_down_sync(0xffffffffu, p, o);
        if (t == 0) s_prefix = p;
    }
    __syncthreads();
    int i = b * SCAN_B + t;
    if (i < N_NODES) {
        int r = g_rowptr[i] + s_prefix;
        g_rowptr[i] = r;
        g_cursor[i] = r;
    }
    if (i == 0) g_rowptr[N_NODES] = N_EDGES;
}

// ---------------- 5: scatter edges into dst-grouped order (packed) --------
__global__ void scatter_kernel(const int* __restrict__ edge_src,
                               const int* __restrict__ edge_dst,
                               const float* __restrict__ edge_weight) {
    int e = blockIdx.x * blockDim.x + threadIdx.x;
    if (e < N_EDGES) {
        int d = __ldg(&edge_dst[e]);
        int s = __ldg(&edge_src[e]);
        float w = __ldg(&edge_weight[e]);
        int pos = atomicAdd(&g_cursor[d], 1);
        g_perm[pos] = make_int2(s, __float_as_int(w));
    }
}

// ---------------- 6: gather-aggregate (16 threads / node) -----------------
// EXACT R4 structure (no smem, no barriers) but packed int2 edge loads.
__global__ void aggregate_kernel() {
    int gt = blockIdx.x * blockDim.x + threadIdx.x;
    int node = gt >> 4;
    int lane = gt & 15;
    if (node >= N_NODES) return;
    int beg = __ldg(&g_rowptr[node]);
    int end = __ldg(&g_rowptr[node + 1]);
    const float4* sup4 = (const float4*)g_support;
    float4 acc = {0.f, 0.f, 0.f, 0.f};

    int e = beg;
    for (; e + 1 < end; e += 2) {       // issue both gathers before consuming
        int2 p0 = __ldg(&g_perm[e]);
        int2 p1 = __ldg(&g_perm[e + 1]);
        float4 v0 = sup4[(size_t)p0.x * 16 + lane];
        float4 v1 = sup4[(size_t)p1.x * 16 + lane];
        float w0 = __int_as_float(p0.y);
        float w1 = __int_as_float(p1.y);
        acc.x += w0 * v0.x; acc.y += w0 * v0.y;
        acc.z += w0 * v0.z; acc.w += w0 * v0.w;
        acc.x += w1 * v1.x; acc.y += w1 * v1.y;
        acc.z += w1 * v1.z; acc.w += w1 * v1.w;
    }
    if (e < end) {
        int2 p = __ldg(&g_perm[e]);
        float w = __int_as_float(p.y);
        float4 v = sup4[(size_t)p.x * 16 + lane];
        acc.x += w * v.x; acc.y += w * v.y;
        acc.z += w * v.z; acc.w += w * v.w;
    }
    ((float4*)g_agg)[(size_t)node * 16 + lane] = acc;
}

// ---------------- 7: batchnorm column statistics (standalone, as R4) ------
__global__ void bnstats_kernel() {
    int c = threadIdx.x & 63;
    int rsub = threadIdx.x >> 6;                     // 0..3
    float s = 0.f, sq = 0.f;
    for (int row = blockIdx.x * 4 + rsub; row < N_NODES; row += gridDim.x * 4) {
        float v = g_agg[(size_t)row * D + c];
        s += v; sq += v * v;
    }
    __shared__ float sh1[256], sh2[256];
    sh1[threadIdx.x] = s; sh2[threadIdx.x] = sq;
    __syncthreads();
    if (threadIdx.x < 64) {
        s  = sh1[c] + sh1[c + 64] + sh1[c + 128] + sh1[c + 192];
        sq = sh2[c] + sh2[c + 64] + sh2[c + 128] + sh2[c + 192];
        atomicAdd(&g_colsum[c], s);
        atomicAdd(&g_colsq[c], sq);
    }
}

// ---------------- 8: finalize BN in-block + normalize + ReLU --------------
// bias cancels with the batch mean, so it never appears.
__global__ void out_kernel(const float* __restrict__ gamma,
                           const float* __restrict__ beta,
                           float* __restrict__ out) {
    __shared__ float s_scale[64], s_shift[64];
    int tid = threadIdx.x;
    if (tid < 64) {
        float mean = g_colsum[tid] * (1.f / N_NODES);
        float var  = g_colsq[tid] * (1.f / N_NODES) - mean * mean;
        float inv  = rsqrtf(var + BN_EPS);
        float sc   = __ldg(&gamma[tid]) * inv;
        s_scale[tid] = sc;
        s_shift[tid] = __ldg(&beta[tid]) - mean * sc;
    }
    __syncthreads();
    int i = blockIdx.x * 256 + tid;            // grid covers N_NODES*16 exactly
    int c = (i & 15) * 4;
    float4 a = ((const float4*)g_agg)[i];
    float4 o;
    o.x = fmaxf(fmaf(a.x, s_scale[c + 0], s_shift[c + 0]), 0.f);
    o.y = fmaxf(fmaf(a.y, s_scale[c + 1], s_shift[c + 1]), 0.f);
    o.z = fmaxf(fmaf(a.z, s_scale[c + 2], s_shift[c + 2]), 0.f);
    o.w = fmaxf(fmaf(a.w, s_scale[c + 3], s_shift[c + 3]), 0.f);
    ((float4*)out)[i] = o;
}

// ---------------- launcher -------------------------------------------------
extern "C" void kernel_launch(void* const* d_in, const int* in_sizes, int n_in,
                              void* d_out, int out_size) {
    const float* x           = (const float*)d_in[0];
    const int*   edge_src    = (const int*)d_in[1];
    const int*   edge_dst    = (const int*)d_in[2];
    const float* edge_weight = (const float*)d_in[3];
    const float* W           = (const float*)d_in[4];
    // d_in[5] = bias: mathematically cancels inside BatchNorm — unused.
    const float* gamma       = (const float*)d_in[6];
    const float* beta        = (const float*)d_in[7];
    float*       out         = (float*)d_out;

    zero_kernel<<<(N_NODES + 255) / 256, 256>>>();
    gemm_kernel<<<N_NODES / 16, 256>>>(x, W);
    hist_kernel<<<(N_EDGES + 511) / 512, 512>>>(edge_dst);
    scan_block_kernel<<<NBLK, SCAN_B>>>();
    add_offsets_kernel<<<NBLK, SCAN_B>>>();
    scatter_kernel<<<(N_EDGES + 511) / 512, 512>>>(edge_src, edge_dst, edge_weight);
    aggregate_kernel<<<N_NODES * 16 / 256, 256>>>();           // 6250 blocks
    bnstats_kernel<<<256, 256>>>();
    out_kernel<<<N_NODES * 16 / 256, 256>>>(gamma, beta, out); // 6250 blocks
}

// round 12
// speedup vs baseline: 1.9815x; 1.0600x over previous
#include <cuda_runtime.h>
#include <cuda_fp16.h>

#define N_NODES 100000
#define N_EDGES 1600000
#define D 64
#define BN_EPS 1e-5f

#define SCAN_B 1024
#define NBLK ((N_NODES + SCAN_B - 1) / SCAN_B)   // 98

// ---------------- device scratch (no allocations allowed) ----------------
__device__ uint2 g_support_h[N_NODES * 16];  // x @ W in fp16 (4 halfs per uint2)
__device__ float g_agg[N_NODES * D];         // aggregated messages (fp32)
__device__ int   g_deg[N_NODES];             // in-degree histogram
__device__ int   g_rowptr[N_NODES + 1];      // CSR row pointers (by dst)
__device__ int   g_cursor[N_NODES];          // scatter write cursors
__device__ int   g_blockSums[128];
__device__ int2  g_perm[N_EDGES];            // packed (src, w-bits), dst-grouped
__device__ float g_colsum[D];
__device__ float g_colsq[D];

// ---------------- 0: zero histogram + stats accumulators ----------------
__global__ void zero_kernel() {
    int i = blockIdx.x * blockDim.x + threadIdx.x;
    if (i < N_NODES) g_deg[i] = 0;
    if (i < D) { g_colsum[i] = 0.f; g_colsq[i] = 0.f; }
}

// ---------------- 1: support = x @ W  (fp32 math, fp16 store) ------------
// block = 256 threads = 16 rows x 16 col-groups (float4-wide per thread)
__global__ void gemm_kernel(const float* __restrict__ x,
                            const float* __restrict__ W) {
    __shared__ float4 Ws4[64 * 16];     // W[k][c] as float4 over c
    __shared__ float  xs[16][65];       // padded to kill bank conflicts

    int tid = threadIdx.x;
    const float4* W4 = (const float4*)W;
    #pragma unroll
    for (int i = tid; i < 1024; i += 256) Ws4[i] = W4[i];

    int row0 = blockIdx.x * 16;
    {   // 16 rows x 64 floats = 256 float4, one per thread
        const float4* x4 = (const float4*)(x + (size_t)row0 * D);
        float4 v = x4[tid];
        int r = tid >> 4, k4 = tid & 15;
        xs[r][k4 * 4 + 0] = v.x; xs[r][k4 * 4 + 1] = v.y;
        xs[r][k4 * 4 + 2] = v.z; xs[r][k4 * 4 + 3] = v.w;
    }
    __syncthreads();

    int r = tid >> 4, c4 = tid & 15;
    float4 acc = {0.f, 0.f, 0.f, 0.f};
    #pragma unroll
    for (int k = 0; k < 64; k++) {
        float xv = xs[r][k];
        float4 w = Ws4[k * 16 + c4];
        acc.x += xv * w.x; acc.y += xv * w.y;
        acc.z += xv * w.z; acc.w += xv * w.w;
    }
    __half2 h0 = __float22half2_rn(make_float2(acc.x, acc.y));
    __half2 h1 = __float22half2_rn(make_float2(acc.z, acc.w));
    uint2 u;
    u.x = *reinterpret_cast<unsigned int*>(&h0);
    u.y = *reinterpret_cast<unsigned int*>(&h1);
    g_support_h[(size_t)(row0 + r) * 16 + c4] = u;
}

// ---------------- 2: histogram of edge destinations ----------------------
__global__ void hist_kernel(const int* __restrict__ edge_dst) {
    int e = blockIdx.x * blockDim.x + threadIdx.x;
    if (e < N_EDGES) atomicAdd(&g_deg[__ldg(&edge_dst[e])], 1);
}

// ---------------- 3: per-block exclusive scan (shuffle-based) -------------
__global__ void scan_block_kernel() {
    __shared__ int warpSum[32];
    int t = threadIdx.x;
    int i = blockIdx.x * SCAN_B + t;
    int v = (i < N_NODES) ? g_deg[i] : 0;
    int lane = t & 31, wid = t >> 5;

    int s = v;                                  // warp inclusive scan
    #pragma unroll
    for (int off = 1; off < 32; off <<= 1) {
        int n = __shfl_up_sync(0xffffffffu, s, off);
        if (lane >= off) s += n;
    }
    if (lane == 31) warpSum[wid] = s;
    __syncthreads();
    if (wid == 0) {                             // scan the 32 warp sums
        int w = warpSum[lane];
        #pragma unroll
        for (int off = 1; off < 32; off <<= 1) {
            int n = __shfl_up_sync(0xffffffffu, w, off);
            if (lane >= off) w += n;
        }
        warpSum[lane] = w;                      // inclusive
    }
    __syncthreads();
    int base = wid ? warpSum[wid - 1] : 0;
    if (i < N_NODES) g_rowptr[i] = base + s - v;         // exclusive in-block
    if (t == SCAN_B - 1) g_blockSums[blockIdx.x] = base + s;
}

// ---------------- 4: add block prefix (computed in-block), init cursors ---
__global__ void add_offsets_kernel() {
    __shared__ int s_prefix;
    int b = blockIdx.x, t = threadIdx.x;
    if (t < 32) {
        int p = 0;
        for (int j = t; j < b; j += 32) p += g_blockSums[j];
        #pragma unroll
        for (int o = 16; o; o >>= 1) p += __shfl_down_sync(0xffffffffu, p, o);
        if (t == 0) s_prefix = p;
    }
    __syncthreads();
    int i = b * SCAN_B + t;
    if (i < N_NODES) {
        int r = g_rowptr[i] + s_prefix;
        g_rowptr[i] = r;
        g_cursor[i] = r;
    }
    if (i == 0) g_rowptr[N_NODES] = N_EDGES;
}

// ---------------- 5: scatter edges into dst-grouped order (packed) --------
__global__ void scatter_kernel(const int* __restrict__ edge_src,
                               const int* __restrict__ edge_dst,
                               const float* __restrict__ edge_weight) {
    int e = blockIdx.x * blockDim.x + threadIdx.x;
    if (e < N_EDGES) {
        int d = __ldg(&edge_dst[e]);
        int s = __ldg(&edge_src[e]);
        float w = __ldg(&edge_weight[e]);
        int pos = atomicAdd(&g_cursor[d], 1);
        g_perm[pos] = make_int2(s, __float_as_int(w));
    }
}

// ---------------- 6: gather-aggregate (16 threads / node) -----------------
// Barrier-free (R10 structure); fp16 support rows halve gather traffic.
// Each lane handles 4 columns = 8 bytes per row.
__global__ void aggregate_kernel() {
    int gt = blockIdx.x * blockDim.x + threadIdx.x;
    int node = gt >> 4;
    int lane = gt & 15;
    if (node >= N_NODES) return;
    int beg = __ldg(&g_rowptr[node]);
    int end = __ldg(&g_rowptr[node + 1]);
    float4 acc = {0.f, 0.f, 0.f, 0.f};

    int e = beg;
    for (; e + 1 < end; e += 2) {       // issue both gathers before consuming
        int2 p0 = __ldg(&g_perm[e]);
        int2 p1 = __ldg(&g_perm[e + 1]);
        uint2 u0 = __ldg(&g_support_h[(size_t)p0.x * 16 + lane]);
        uint2 u1 = __ldg(&g_support_h[(size_t)p1.x * 16 + lane]);
        float w0 = __int_as_float(p0.y);
        float w1 = __int_as_float(p1.y);
        float2 a0 = __half22float2(*reinterpret_cast<__half2*>(&u0.x));
        float2 b0 = __half22float2(*reinterpret_cast<__half2*>(&u0.y));
        float2 a1 = __half22float2(*reinterpret_cast<__half2*>(&u1.x));
        float2 b1 = __half22float2(*reinterpret_cast<__half2*>(&u1.y));
        acc.x += w0 * a0.x; acc.y += w0 * a0.y;
        acc.z += w0 * b0.x; acc.w += w0 * b0.y;
        acc.x += w1 * a1.x; acc.y += w1 * a1.y;
        acc.z += w1 * b1.x; acc.w += w1 * b1.y;
    }
    if (e < end) {
        int2 p = __ldg(&g_perm[e]);
        float w = __int_as_float(p.y);
        uint2 u = __ldg(&g_support_h[(size_t)p.x * 16 + lane]);
        float2 a = __half22float2(*reinterpret_cast<__half2*>(&u.x));
        float2 b = __half22float2(*reinterpret_cast<__half2*>(&u.y));
        acc.x += w * a.x; acc.y += w * a.y;
        acc.z += w * b.x; acc.w += w * b.y;
    }
    ((float4*)g_agg)[(size_t)node * 16 + lane] = acc;
}

// ---------------- 7: batchnorm column statistics (standalone) -------------
__global__ void bnstats_kernel() {
    int c = threadIdx.x & 63;
    int rsub = threadIdx.x >> 6;                     // 0..3
    float s = 0.f, sq = 0.f;
    for (int row = blockIdx.x * 4 + rsub; row < N_NODES; row += gridDim.x * 4) {
        float v = g_agg[(size_t)row * D + c];
        s += v; sq += v * v;
    }
    __shared__ float sh1[256], sh2[256];
    sh1[threadIdx.x] = s; sh2[threadIdx.x] = sq;
    __syncthreads();
    if (threadIdx.x < 64) {
        s  = sh1[c] + sh1[c + 64] + sh1[c + 128] + sh1[c + 192];
        sq = sh2[c] + sh2[c + 64] + sh2[c + 128] + sh2[c + 192];
        atomicAdd(&g_colsum[c], s);
        atomicAdd(&g_colsq[c], sq);
    }
}

// ---------------- 8: finalize BN in-block + normalize + ReLU --------------
// bias cancels with the batch mean, so it never appears.
__global__ void out_kernel(const float* __restrict__ gamma,
                           const float* __restrict__ beta,
                           float* __restrict__ out) {
    __shared__ float s_scale[64], s_shift[64];
    int tid = threadIdx.x;
    if (tid < 64) {
        float mean = g_colsum[tid] * (1.f / N_NODES);
        float var  = g_colsq[tid] * (1.f / N_NODES) - mean * mean;
        float inv  = rsqrtf(var + BN_EPS);
        float sc   = __ldg(&gamma[tid]) * inv;
        s_scale[tid] = sc;
        s_shift[tid] = __ldg(&beta[tid]) - mean * sc;
    }
    __syncthreads();
    int i = blockIdx.x * 256 + tid;            // grid covers N_NODES*16 exactly
    int c = (i & 15) * 4;
    float4 a = ((const float4*)g_agg)[i];
    float4 o;
    o.x = fmaxf(fmaf(a.x, s_scale[c + 0], s_shift[c + 0]), 0.f);
    o.y = fmaxf(fmaf(a.y, s_scale[c + 1], s_shift[c + 1]), 0.f);
    o.z = fmaxf(fmaf(a.z, s_scale[c + 2], s_shift[c + 2]), 0.f);
    o.w = fmaxf(fmaf(a.w, s_scale[c + 3], s_shift[c + 3]), 0.f);
    ((float4*)out)[i] = o;
}

// ---------------- launcher -------------------------------------------------
extern "C" void kernel_launch(void* const* d_in, const int* in_sizes, int n_in,
                              void* d_out, int out_size) {
    const float* x           = (const float*)d_in[0];
    const int*   edge_src    = (const int*)d_in[1];
    const int*   edge_dst    = (const int*)d_in[2];
    const float* edge_weight = (const float*)d_in[3];
    const float* W           = (const float*)d_in[4];
    // d_in[5] = bias: mathematically cancels inside BatchNorm — unused.
    const float* gamma       = (const float*)d_in[6];
    const float* beta        = (const float*)d_in[7];
    float*       out         = (float*)d_out;

    zero_kernel<<<(N_NODES + 255) / 256, 256>>>();
    gemm_kernel<<<N_NODES / 16, 256>>>(x, W);
    hist_kernel<<<(N_EDGES + 511) / 512, 512>>>(edge_dst);
    scan_block_kernel<<<NBLK, SCAN_B>>>();
    add_offsets_kernel<<<NBLK, SCAN_B>>>();
    scatter_kernel<<<(N_EDGES + 511) / 512, 512>>>(edge_src, edge_dst, edge_weight);
    aggregate_kernel<<<N_NODES * 16 / 256, 256>>>();           // 6250 blocks
    bnstats_kernel<<<256, 256>>>();
    out_kernel<<<N_NODES * 16 / 256, 256>>>(gamma, beta, out); // 6250 blocks
}